// round 14
// baseline (speedup 1.0000x reference)
#include <cuda_runtime.h>
#include <math.h>

#define NXc 201
#define NYc 121
#define NZc 80
#define VPB (NXc * NYc * NZc)      // 1,945,680 voxels per batch item
#define BATCH 4
#define NPAIR 2
#define HH 512
#define WW 1024
#define NPTS (HH * WW)             // 2^19 points per batch
#define TOT (BATCH * NPTS)
#define QB (NPTS / 4)              // quads per batch = 2^17
#define QP (NPAIR * QB)            // quads per pair  = 262,144
#define LOG32F 3.4657359027997265f

// Ping-pong pair-sized accumulators (62 MB each). accA serves pair 0,
// accB serves pair 1. INVARIANT: pair p's accumulator is all-zero when
// scatter(p) runs. Established: zero-init at load; maintained: scatter(p)
// clears the OTHER pair's accumulator using the persisted seg values of that
// pair (from this launch for p=1, from the previous replay for p=0 --
// correct in both cases, and a harmless no-op write of zeros on first call).
__device__ float4 g_accA[NPAIR * VPB];
__device__ float4 g_accB[NPAIR * VPB];
__device__ int    g_seg[TOT];      // persisted across replays (load-bearing!)
__device__ unsigned int g_min[BATCH];
__device__ unsigned int g_max[BATCH];

__device__ __forceinline__ unsigned long long plc_last() {
    unsigned long long p;
    asm("createpolicy.fractional.L2::evict_last.b64 %0, 1.0;" : "=l"(p));
    return p;
}

__device__ __forceinline__ void red_add_v4(float4* addr, float c, float z, float r, float g,
                                           unsigned long long pol) {
    asm volatile("red.global.add.L2::cache_hint.v4.f32 [%0], {%1, %2, %3, %4}, %5;"
                 :: "l"(addr), "f"(c), "f"(z), "f"(r), "f"(g), "l"(pol) : "memory");
}

__device__ __forceinline__ float4 ld_acc(const float4* addr, unsigned long long pol) {
    float4 v;
    asm("ld.global.nc.L2::cache_hint.v4.f32 {%0, %1, %2, %3}, [%4], %5;"
        : "=f"(v.x), "=f"(v.y), "=f"(v.z), "=f"(v.w) : "l"(addr), "l"(pol));
    return v;
}

__device__ __forceinline__ void st_acc_zero(float4* addr, unsigned long long pol) {
    asm volatile("st.global.L2::cache_hint.v4.f32 [%0], {%1, %1, %1, %1}, %2;"
                 :: "l"(addr), "f"(0.0f), "l"(pol) : "memory");
}

// ------ K1: scatter pair p into its acc + clear the other pair's acc --------
__global__ void k_scatter(const float* __restrict__ xyz,
                          const float4* __restrict__ rel4,
                          const float4* __restrict__ geom4, int p) {
    int i = blockIdx.x * blockDim.x + threadIdx.x;   // quad index within pair
    if (i < NPAIR) {             // re-arm this pair's min/max (consumed by k_mx)
        g_min[2 * p + i] = 0x7F800000u;
        g_max[2 * p + i] = 0u;
    }
    if (i >= QP) return;
    unsigned long long pol = plc_last();
    float4* cur = (p == 0) ? g_accA : g_accB;
    float4* oth = (p == 0) ? g_accB : g_accA;
    int bl = i >> 17;                    // batch within pair
    int qo = i & (QB - 1);               // quad within batch

    // ---- clear the other pair's touched voxels (independent latency work,
    //      overlaps with this pair's stream loads below) ----
    {
        int gio = (2 * (p ^ 1) + bl) * QB + qo;
        int4 so = __ldcs((const int4*)g_seg + gio);
        if (so.x >= 0) st_acc_zero(&oth[so.x], pol);
        if (so.y >= 0) st_acc_zero(&oth[so.y], pol);
        if (so.z >= 0) st_acc_zero(&oth[so.z], pol);
        if (so.w >= 0) st_acc_zero(&oth[so.w], pol);
    }

    // ---- scatter this pair ----
    int b  = 2 * p + bl;
    int p4 = qo << 2;
    const float* base = xyz + (long long)b * 3 * NPTS;
    float4 x = __ldcs((const float4*)(base + p4));
    float4 y = __ldcs((const float4*)(base + p4 + NPTS));
    float4 z = __ldcs((const float4*)(base + p4 + 2 * NPTS));
    int gi = b * QB + qo;
    float4 r = __ldcs(rel4 + gi);
    float4 g = __ldcs(geom4 + gi);

    int seg[4];
    float xs[4] = {x.x, x.y, x.z, x.w};
    float ys[4] = {y.x, y.y, y.z, y.w};
    float zs[4] = {z.x, z.y, z.z, z.w};
    float rs[4] = {r.x, r.y, r.z, r.w};

    #pragma unroll
    for (int k = 0; k < 4; k++) {
        bool keep = (xs[k] >= -10.0f) & (xs[k] <= 10.0f) &
                    (ys[k] >= -6.0f)  & (ys[k] <= 6.0f)  &
                    (zs[k] >= 0.3f)   & (zs[k] <= 20.0f) &
                    (rs[k] > 0.0f);
        seg[k] = -1;
        if (keep) {
            // Bit-exact vs XLA: (v - lo) * round_f32(1/c); 1/0.1f -> 10.0,
            // 1/0.25f -> 4.0, both exact in f32. DO NOT CHANGE.
            float fx = floorf(__fmul_rn(__fadd_rn(xs[k], 10.0f), 10.0f));
            float fy = floorf(__fmul_rn(__fadd_rn(ys[k], 6.0f),  10.0f));
            float fz = floorf(__fmul_rn(__fsub_rn(zs[k], 0.3f),  4.0f));
            int ix = min(max((int)fx, 0), NXc - 1);
            int iy = min(max((int)fy, 0), NYc - 1);
            int iz = min(max((int)fz, 0), NZc - 1);
            seg[k] = (ix * NYc + iy) * NZc + iz + bl * VPB;   // local to pair
        }
    }
    float gs[4] = {g.x, g.y, g.z, g.w};
    #pragma unroll
    for (int k = 0; k < 4; k++)
        if (seg[k] >= 0)
            red_add_v4(&cur[seg[k]], 1.0f, zs[k], rs[k], gs[k], pol);

    __stcs((int4*)g_seg + gi, make_int4(seg[0], seg[1], seg[2], seg[3]));
}

// shared score math
__device__ __forceinline__ float voxel_score(float4 a) {
    float cc  = fmaxf(a.x, 1.0f);
    float inv = __fdividef(1.0f, cc);
    float z_mean    = a.y * inv;
    float rel_mean  = a.z * inv;
    float geom_mean = a.w * inv;
    float density   = log1pf(a.x) * (1.0f / LOG32F);
    float range_sc  = __expf(-0.08f * z_mean);
    float t = 0.55f * geom_mean + 0.25f * density + 0.2f * range_sc;
    return fmaxf(t * rel_mean, 0.0f);
}

// ------ K2: per-batch min/max of scores (no out write) ----------------------
__global__ void k_mx(int p) {
    int i = blockIdx.x * blockDim.x + threadIdx.x;
    const float4* acc = (p == 0) ? g_accA : g_accB;
    float s[4] = {0.f, 0.f, 0.f, 0.f};
    int b = 2 * p + ((blockIdx.x * blockDim.x) >> 17);  // block within 1 batch
    if (i < QP) {
        unsigned long long pol = plc_last();
        int gi = b * QB + (i & (QB - 1));
        int4 sg = __ldcs((const int4*)g_seg + gi);
        int seg[4] = {sg.x, sg.y, sg.z, sg.w};
        float4 a[4];
        #pragma unroll
        for (int k = 0; k < 4; k++)
            a[k] = (seg[k] >= 0) ? ld_acc(&acc[seg[k]], pol)
                                 : make_float4(0.f, 0.f, 0.f, 0.f);
        #pragma unroll
        for (int k = 0; k < 4; k++)
            if (seg[k] >= 0) s[k] = voxel_score(a[k]);
    }

    float vmin = __int_as_float(0x7F800000), vmax = 0.0f;
    if (i < QP) {
        vmin = fminf(fminf(s[0], s[1]), fminf(s[2], s[3]));
        vmax = fmaxf(fmaxf(s[0], s[1]), fmaxf(s[2], s[3]));
    }
    #pragma unroll
    for (int off = 16; off > 0; off >>= 1) {
        vmin = fminf(vmin, __shfl_xor_sync(0xFFFFFFFFu, vmin, off));
        vmax = fmaxf(vmax, __shfl_xor_sync(0xFFFFFFFFu, vmax, off));
    }
    __shared__ float smin[8], smax[8];
    int warp = threadIdx.x >> 5;
    int lane = threadIdx.x & 31;
    if (lane == 0) { smin[warp] = vmin; smax[warp] = vmax; }
    __syncthreads();
    if (threadIdx.x == 0) {
        float bmin = smin[0], bmax = smax[0];
        #pragma unroll
        for (int w = 1; w < 8; w++) {
            bmin = fminf(bmin, smin[w]);
            bmax = fmaxf(bmax, smax[w]);
        }
        atomicMin(&g_min[b], __float_as_uint(bmin));
        atomicMax(&g_max[b], __float_as_uint(bmax));
    }
}

// ------ K3: gather (L2 hot) + score + normalize + single out write ----------
__global__ void k_final(float4* __restrict__ out4, int p) {
    int i = blockIdx.x * blockDim.x + threadIdx.x;
    if (i >= QP) return;
    unsigned long long pol = plc_last();
    const float4* acc = (p == 0) ? g_accA : g_accB;
    int b  = 2 * p + (i >> 17);
    int gi = b * QB + (i & (QB - 1));
    int4 sg = __ldcs((const int4*)g_seg + gi);
    int seg[4] = {sg.x, sg.y, sg.z, sg.w};
    float4 a[4];
    #pragma unroll
    for (int k = 0; k < 4; k++)
        a[k] = (seg[k] >= 0) ? ld_acc(&acc[seg[k]], pol)
                             : make_float4(0.f, 0.f, 0.f, 0.f);
    float s[4];
    #pragma unroll
    for (int k = 0; k < 4; k++)
        s[k] = (seg[k] >= 0) ? voxel_score(a[k]) : 0.0f;

    float mn = __uint_as_float(g_min[b]);
    float mx = __uint_as_float(g_max[b]);
    float inv = __fdividef(1.0f, (mx - mn) + 1e-6f);
    __stcs(out4 + gi, make_float4((s[0] - mn) * inv, (s[1] - mn) * inv,
                                  (s[2] - mn) * inv, (s[3] - mn) * inv));
}

extern "C" void kernel_launch(void* const* d_in, const int* in_sizes, int n_in,
                              void* d_out, int out_size) {
    const float* xyz  = (const float*)d_in[0];
    const float* rel  = (const float*)d_in[1];
    const float* geom = (const float*)d_in[2];
    float* out = (float*)d_out;

    const int T = 256;
    const int G = QP / T;   // 1024 blocks
    for (int p = 0; p < BATCH / NPAIR; p++) {
        k_scatter<<<G, T>>>(xyz, (const float4*)rel, (const float4*)geom, p);
        k_mx<<<G, T>>>(p);
        k_final<<<G, T>>>((float4*)out, p);
    }
}

// round 15
// speedup vs baseline: 1.1231x; 1.1231x over previous
#include <cuda_runtime.h>
#include <math.h>

#define NXc 201
#define NYc 121
#define NZc 80
#define VPB (NXc * NYc * NZc)      // 1,945,680 voxels per batch item
#define BATCH 4
#define NPAIR 2
#define HH 512
#define WW 1024
#define NPTS (HH * WW)             // 2^19 points per batch
#define TOT (BATCH * NPTS)
#define QB (NPTS / 4)              // quads per batch = 2^17
#define QP (NPAIR * QB)            // quads per pair  = 262,144
#define LOG32F 3.4657359027997265f

// Single pair-sized accumulator (62 MB -> L2-resident with evict_last),
// reused across the 2 phases. INVARIANT: all-zero on entry to each scatter
// (zero-init at load; re-established by k_clear of the previous phase).
__device__ float4 g_acc[NPAIR * VPB];
__device__ int    g_seg[TOT];
__device__ unsigned int g_min[BATCH];
__device__ unsigned int g_max[BATCH];

__device__ __forceinline__ unsigned long long plc_last() {
    unsigned long long p;
    asm("createpolicy.fractional.L2::evict_last.b64 %0, 1.0;" : "=l"(p));
    return p;
}

__device__ __forceinline__ void red_add_v4(float4* addr, float c, float z, float r, float g,
                                           unsigned long long pol) {
    asm volatile("red.global.add.L2::cache_hint.v4.f32 [%0], {%1, %2, %3, %4}, %5;"
                 :: "l"(addr), "f"(c), "f"(z), "f"(r), "f"(g), "l"(pol) : "memory");
}

__device__ __forceinline__ float4 ld_acc(const float4* addr, unsigned long long pol) {
    float4 v;
    asm("ld.global.nc.L2::cache_hint.v4.f32 {%0, %1, %2, %3}, [%4], %5;"
        : "=f"(v.x), "=f"(v.y), "=f"(v.z), "=f"(v.w) : "l"(addr), "l"(pol));
    return v;
}

__device__ __forceinline__ void st_acc_zero(float4* addr, unsigned long long pol) {
    asm volatile("st.global.L2::cache_hint.v4.f32 [%0], {%1, %1, %1, %1}, %2;"
                 :: "l"(addr), "f"(0.0f), "l"(pol) : "memory");
}

// ---------------- K1: scatter one PAIR of batch items (R11-proven) ----------
__global__ void k_scatter(const float* __restrict__ xyz,
                          const float4* __restrict__ rel4,
                          const float4* __restrict__ geom4, int p) {
    int i = blockIdx.x * blockDim.x + threadIdx.x;   // quad index within pair
    if (i < NPAIR) {             // re-arm this pair's min/max (consumed by k_mx)
        g_min[2 * p + i] = 0x7F800000u;
        g_max[2 * p + i] = 0u;
    }
    if (i >= QP) return;
    unsigned long long pol = plc_last();
    int bl = i >> 17;
    int b  = 2 * p + bl;
    int p4 = (i << 2) & (NPTS - 1);
    const float* base = xyz + (long long)b * 3 * NPTS;
    float4 x = __ldcs((const float4*)(base + p4));
    float4 y = __ldcs((const float4*)(base + p4 + NPTS));
    float4 z = __ldcs((const float4*)(base + p4 + 2 * NPTS));
    int gi = b * QB + (i & (QB - 1));
    float4 r = __ldcs(rel4 + gi);
    float4 g = __ldcs(geom4 + gi);

    int seg[4];
    float xs[4] = {x.x, x.y, x.z, x.w};
    float ys[4] = {y.x, y.y, y.z, y.w};
    float zs[4] = {z.x, z.y, z.z, z.w};
    float rs[4] = {r.x, r.y, r.z, r.w};

    #pragma unroll
    for (int k = 0; k < 4; k++) {
        bool keep = (xs[k] >= -10.0f) & (xs[k] <= 10.0f) &
                    (ys[k] >= -6.0f)  & (ys[k] <= 6.0f)  &
                    (zs[k] >= 0.3f)   & (zs[k] <= 20.0f) &
                    (rs[k] > 0.0f);
        seg[k] = -1;
        if (keep) {
            // Bit-exact vs XLA: (v - lo) * round_f32(1/c); 1/0.1f -> 10.0,
            // 1/0.25f -> 4.0, both exact in f32. DO NOT CHANGE.
            float fx = floorf(__fmul_rn(__fadd_rn(xs[k], 10.0f), 10.0f));
            float fy = floorf(__fmul_rn(__fadd_rn(ys[k], 6.0f),  10.0f));
            float fz = floorf(__fmul_rn(__fsub_rn(zs[k], 0.3f),  4.0f));
            int ix = min(max((int)fx, 0), NXc - 1);
            int iy = min(max((int)fy, 0), NYc - 1);
            int iz = min(max((int)fz, 0), NZc - 1);
            seg[k] = (ix * NYc + iy) * NZc + iz + bl * VPB;   // local to pair
        }
    }
    float gs[4] = {g.x, g.y, g.z, g.w};
    #pragma unroll
    for (int k = 0; k < 4; k++)
        if (seg[k] >= 0)
            red_add_v4(&g_acc[seg[k]], 1.0f, zs[k], rs[k], gs[k], pol);

    __stcs((int4*)g_seg + gi, make_int4(seg[0], seg[1], seg[2], seg[3]));
}

// shared score math
__device__ __forceinline__ float voxel_score(float4 a) {
    float cc  = fmaxf(a.x, 1.0f);
    float inv = __fdividef(1.0f, cc);
    float z_mean    = a.y * inv;
    float rel_mean  = a.z * inv;
    float geom_mean = a.w * inv;
    float density   = log1pf(a.x) * (1.0f / LOG32F);
    float range_sc  = __expf(-0.08f * z_mean);
    float t = 0.55f * geom_mean + 0.25f * density + 0.2f * range_sc;
    return fmaxf(t * rel_mean, 0.0f);
}

// ------ K2: per-batch min/max of scores (no out write) ----------------------
__global__ void k_mx(int p) {
    int i = blockIdx.x * blockDim.x + threadIdx.x;
    float s[4] = {0.f, 0.f, 0.f, 0.f};
    int b = 2 * p + ((blockIdx.x * blockDim.x) >> 17);  // block within 1 batch
    if (i < QP) {
        unsigned long long pol = plc_last();
        int gi = b * QB + (i & (QB - 1));
        int4 sg = __ldcs((const int4*)g_seg + gi);
        int seg[4] = {sg.x, sg.y, sg.z, sg.w};
        float4 a[4];
        #pragma unroll
        for (int k = 0; k < 4; k++)
            a[k] = (seg[k] >= 0) ? ld_acc(&g_acc[seg[k]], pol)
                                 : make_float4(0.f, 0.f, 0.f, 0.f);
        #pragma unroll
        for (int k = 0; k < 4; k++)
            if (seg[k] >= 0) s[k] = voxel_score(a[k]);
    }

    float vmin = __int_as_float(0x7F800000), vmax = 0.0f;
    if (i < QP) {
        vmin = fminf(fminf(s[0], s[1]), fminf(s[2], s[3]));
        vmax = fmaxf(fmaxf(s[0], s[1]), fmaxf(s[2], s[3]));
    }
    #pragma unroll
    for (int off = 16; off > 0; off >>= 1) {
        vmin = fminf(vmin, __shfl_xor_sync(0xFFFFFFFFu, vmin, off));
        vmax = fmaxf(vmax, __shfl_xor_sync(0xFFFFFFFFu, vmax, off));
    }
    __shared__ float smin[8], smax[8];
    int warp = threadIdx.x >> 5;
    int lane = threadIdx.x & 31;
    if (lane == 0) { smin[warp] = vmin; smax[warp] = vmax; }
    __syncthreads();
    if (threadIdx.x == 0) {
        float bmin = smin[0], bmax = smax[0];
        #pragma unroll
        for (int w = 1; w < 8; w++) {
            bmin = fminf(bmin, smin[w]);
            bmax = fmaxf(bmax, smax[w]);
        }
        atomicMin(&g_min[b], __float_as_uint(bmin));
        atomicMax(&g_max[b], __float_as_uint(bmax));
    }
}

// ------ K3: re-gather (L2 hot) + score + normalize + single out write -------
__global__ void k_final(float4* __restrict__ out4, int p) {
    int i = blockIdx.x * blockDim.x + threadIdx.x;
    if (i >= QP) return;
    unsigned long long pol = plc_last();
    int b  = 2 * p + (i >> 17);
    int gi = b * QB + (i & (QB - 1));
    int4 sg = __ldcs((const int4*)g_seg + gi);
    int seg[4] = {sg.x, sg.y, sg.z, sg.w};
    float4 a[4];
    #pragma unroll
    for (int k = 0; k < 4; k++)
        a[k] = (seg[k] >= 0) ? ld_acc(&g_acc[seg[k]], pol)
                             : make_float4(0.f, 0.f, 0.f, 0.f);
    float s[4];
    #pragma unroll
    for (int k = 0; k < 4; k++)
        s[k] = (seg[k] >= 0) ? voxel_score(a[k]) : 0.0f;

    float mn = __uint_as_float(g_min[b]);
    float mx = __uint_as_float(g_max[b]);
    float inv = __fdividef(1.0f, (mx - mn) + 1e-6f);
    __stcs(out4 + gi, make_float4((s[0] - mn) * inv, (s[1] - mn) * inv,
                                  (s[2] - mn) * inv, (s[3] - mn) * inv));
}

// ------ K4: restore acc invariant for this pair ------------------------------
__global__ void k_clear(int p) {
    int i = blockIdx.x * blockDim.x + threadIdx.x;
    if (i >= QP) return;
    unsigned long long pol = plc_last();
    int b  = 2 * p + (i >> 17);
    int gi = b * QB + (i & (QB - 1));
    int4 sg = __ldcs((const int4*)g_seg + gi);
    if (sg.x >= 0) st_acc_zero(&g_acc[sg.x], pol);
    if (sg.y >= 0) st_acc_zero(&g_acc[sg.y], pol);
    if (sg.z >= 0) st_acc_zero(&g_acc[sg.z], pol);
    if (sg.w >= 0) st_acc_zero(&g_acc[sg.w], pol);
}

extern "C" void kernel_launch(void* const* d_in, const int* in_sizes, int n_in,
                              void* d_out, int out_size) {
    const float* xyz  = (const float*)d_in[0];
    const float* rel  = (const float*)d_in[1];
    const float* geom = (const float*)d_in[2];
    float* out = (float*)d_out;

    const int T = 256;
    const int G = QP / T;   // 1024 blocks
    for (int p = 0; p < BATCH / NPAIR; p++) {
        k_scatter<<<G, T>>>(xyz, (const float4*)rel, (const float4*)geom, p);
        k_mx<<<G, T>>>(p);
        k_final<<<G, T>>>((float4*)out, p);
        k_clear<<<G, T>>>(p);
    }
}

// round 16
// speedup vs baseline: 1.3774x; 1.2264x over previous
#include <cuda_runtime.h>
#include <math.h>

#define NXc 201
#define NYc 121
#define NZc 80
#define VPB (NXc * NYc * NZc)      // 1,945,680 voxels per batch item
#define BATCH 4
#define HH 512
#define WW 1024
#define NPTS (HH * WW)             // 2^19 points per batch
#define TOT (BATCH * NPTS)
#define QB (NPTS / 4)              // quads per batch = 131,072
#define LOG32F 3.4657359027997265f

// Two batch-sized accumulator halves (31 MB each, 62 MB total -> L2-friendly).
// Stream A (batches 0,2) owns half 0; stream B (batches 1,3) owns half 1.
// INVARIANT: a half is all-zero when its next scatter runs (zero-init at load;
// re-established by k_norm_clear of the previous batch on the SAME stream).
__device__ float4 g_acc[2 * VPB];
__device__ int    g_seg[TOT];
__device__ unsigned int g_min[BATCH];
__device__ unsigned int g_max[BATCH];

__device__ __forceinline__ unsigned long long plc_last() {
    unsigned long long p;
    asm("createpolicy.fractional.L2::evict_last.b64 %0, 1.0;" : "=l"(p));
    return p;
}

__device__ __forceinline__ void red_add_v4(float4* addr, float c, float z, float r, float g,
                                           unsigned long long pol) {
    asm volatile("red.global.add.L2::cache_hint.v4.f32 [%0], {%1, %2, %3, %4}, %5;"
                 :: "l"(addr), "f"(c), "f"(z), "f"(r), "f"(g), "l"(pol) : "memory");
}

__device__ __forceinline__ float4 ld_acc(const float4* addr, unsigned long long pol) {
    float4 v;
    asm("ld.global.nc.L2::cache_hint.v4.f32 {%0, %1, %2, %3}, [%4], %5;"
        : "=f"(v.x), "=f"(v.y), "=f"(v.z), "=f"(v.w) : "l"(addr), "l"(pol));
    return v;
}

__device__ __forceinline__ void st_acc_zero(float4* addr, unsigned long long pol) {
    asm volatile("st.global.L2::cache_hint.v4.f32 [%0], {%1, %1, %1, %1}, %2;"
                 :: "l"(addr), "f"(0.0f), "l"(pol) : "memory");
}

// ---------------- K1: scatter one batch item into its acc half --------------
__global__ void k_scatter(const float* __restrict__ xyz,
                          const float4* __restrict__ rel4,
                          const float4* __restrict__ geom4, int b) {
    int i = blockIdx.x * blockDim.x + threadIdx.x;   // quad index within batch
    if (i == 0) {               // re-arm this batch's min/max (consumed by k_score)
        g_min[b] = 0x7F800000u;
        g_max[b] = 0u;
    }
    if (i >= QB) return;
    unsigned long long pol = plc_last();
    int half = (b & 1) * VPB;
    int p4 = i << 2;
    const float* base = xyz + (long long)b * 3 * NPTS;
    float4 x = __ldcs((const float4*)(base + p4));
    float4 y = __ldcs((const float4*)(base + p4 + NPTS));
    float4 z = __ldcs((const float4*)(base + p4 + 2 * NPTS));
    int gi = b * QB + i;
    float4 r = __ldcs(rel4 + gi);
    float4 g = __ldcs(geom4 + gi);

    int seg[4];
    float xs[4] = {x.x, x.y, x.z, x.w};
    float ys[4] = {y.x, y.y, y.z, y.w};
    float zs[4] = {z.x, z.y, z.z, z.w};
    float rs[4] = {r.x, r.y, r.z, r.w};

    #pragma unroll
    for (int k = 0; k < 4; k++) {
        bool keep = (xs[k] >= -10.0f) & (xs[k] <= 10.0f) &
                    (ys[k] >= -6.0f)  & (ys[k] <= 6.0f)  &
                    (zs[k] >= 0.3f)   & (zs[k] <= 20.0f) &
                    (rs[k] > 0.0f);
        seg[k] = -1;
        if (keep) {
            // Bit-exact vs XLA: (v - lo) * round_f32(1/c); 1/0.1f -> 10.0,
            // 1/0.25f -> 4.0, both exact in f32. DO NOT CHANGE.
            float fx = floorf(__fmul_rn(__fadd_rn(xs[k], 10.0f), 10.0f));
            float fy = floorf(__fmul_rn(__fadd_rn(ys[k], 6.0f),  10.0f));
            float fz = floorf(__fmul_rn(__fsub_rn(zs[k], 0.3f),  4.0f));
            int ix = min(max((int)fx, 0), NXc - 1);
            int iy = min(max((int)fy, 0), NYc - 1);
            int iz = min(max((int)fz, 0), NZc - 1);
            seg[k] = (ix * NYc + iy) * NZc + iz + half;    // within acc half
        }
    }
    float gs[4] = {g.x, g.y, g.z, g.w};
    #pragma unroll
    for (int k = 0; k < 4; k++)
        if (seg[k] >= 0)
            red_add_v4(&g_acc[seg[k]], 1.0f, zs[k], rs[k], gs[k], pol);

    __stcs((int4*)g_seg + gi, make_int4(seg[0], seg[1], seg[2], seg[3]));
}

// ---------------- K2: gather + score + batch min/max -------------------------
__global__ void k_score(float4* __restrict__ out4, int b) {
    int i = blockIdx.x * blockDim.x + threadIdx.x;
    float s[4] = {0.f, 0.f, 0.f, 0.f};
    if (i < QB) {
        unsigned long long pol = plc_last();
        int gi = b * QB + i;
        int4 sg = __ldcs((const int4*)g_seg + gi);
        int seg[4] = {sg.x, sg.y, sg.z, sg.w};
        float4 a[4];
        #pragma unroll
        for (int k = 0; k < 4; k++)
            a[k] = (seg[k] >= 0) ? ld_acc(&g_acc[seg[k]], pol)
                                 : make_float4(0.f, 0.f, 0.f, 0.f);
        #pragma unroll
        for (int k = 0; k < 4; k++) {
            if (seg[k] >= 0) {
                float cc  = fmaxf(a[k].x, 1.0f);
                float inv = __fdividef(1.0f, cc);
                float z_mean    = a[k].y * inv;
                float rel_mean  = a[k].z * inv;
                float geom_mean = a[k].w * inv;
                float density   = log1pf(a[k].x) * (1.0f / LOG32F);
                float range_sc  = __expf(-0.08f * z_mean);
                float t = 0.55f * geom_mean + 0.25f * density + 0.2f * range_sc;
                s[k] = fmaxf(t * rel_mean, 0.0f);
            }
        }
        __stcs(out4 + gi, make_float4(s[0], s[1], s[2], s[3]));
    }

    float vmin = __int_as_float(0x7F800000), vmax = 0.0f;
    if (i < QB) {
        vmin = fminf(fminf(s[0], s[1]), fminf(s[2], s[3]));
        vmax = fmaxf(fmaxf(s[0], s[1]), fmaxf(s[2], s[3]));
    }
    #pragma unroll
    for (int off = 16; off > 0; off >>= 1) {
        vmin = fminf(vmin, __shfl_xor_sync(0xFFFFFFFFu, vmin, off));
        vmax = fmaxf(vmax, __shfl_xor_sync(0xFFFFFFFFu, vmax, off));
    }
    __shared__ float smin[8], smax[8];
    int warp = threadIdx.x >> 5;
    int lane = threadIdx.x & 31;
    if (lane == 0) { smin[warp] = vmin; smax[warp] = vmax; }
    __syncthreads();
    if (threadIdx.x == 0) {
        float bmin = smin[0], bmax = smax[0];
        #pragma unroll
        for (int w = 1; w < 8; w++) {
            bmin = fminf(bmin, smin[w]);
            bmax = fmaxf(bmax, smax[w]);
        }
        atomicMin(&g_min[b], __float_as_uint(bmin));
        atomicMax(&g_max[b], __float_as_uint(bmax));
    }
}

// ---------------- K3: normalize batch + restore acc-half invariant -----------
__global__ void k_norm_clear(float4* __restrict__ out4, int b) {
    int i = blockIdx.x * blockDim.x + threadIdx.x;
    if (i >= QB) return;
    unsigned long long pol = plc_last();
    int gi = b * QB + i;

    int4 sg = __ldcs((const int4*)g_seg + gi);
    if (sg.x >= 0) st_acc_zero(&g_acc[sg.x], pol);
    if (sg.y >= 0) st_acc_zero(&g_acc[sg.y], pol);
    if (sg.z >= 0) st_acc_zero(&g_acc[sg.z], pol);
    if (sg.w >= 0) st_acc_zero(&g_acc[sg.w], pol);

    float mn = __uint_as_float(g_min[b]);
    float mx = __uint_as_float(g_max[b]);
    float inv = __fdividef(1.0f, (mx - mn) + 1e-6f);
    float4 v = __ldcs(out4 + gi);
    v.x = (v.x - mn) * inv;
    v.y = (v.y - mn) * inv;
    v.z = (v.z - mn) * inv;
    v.w = (v.w - mn) * inv;
    __stcs(out4 + gi, v);
}

extern "C" void kernel_launch(void* const* d_in, const int* in_sizes, int n_in,
                              void* d_out, int out_size) {
    const float* xyz  = (const float*)d_in[0];
    const float* rel  = (const float*)d_in[1];
    const float* geom = (const float*)d_in[2];
    float* out = (float*)d_out;

    // Second stream for the independent batch pipeline {1,3}. Host objects
    // only (no device memory). kernel_launch is invoked only a handful of
    // times (correctness + capture), so creating per call is safe.
    cudaStream_t sB;
    cudaStreamCreate(&sB);
    cudaEvent_t eFork, eJoin;
    cudaEventCreateWithFlags(&eFork, cudaEventDisableTiming);
    cudaEventCreateWithFlags(&eJoin, cudaEventDisableTiming);

    const int T = 256;
    const int G = QB / T;   // 512 blocks per kernel

    // fork: stream B branches off the (possibly capturing) default stream
    cudaEventRecord(eFork, 0);
    cudaStreamWaitEvent(sB, eFork, 0);

    // pipeline A: batches 0, 2 on default stream (acc half 0)
    // pipeline B: batches 1, 3 on sB            (acc half 1)
    for (int j = 0; j < 2; j++) {
        int bA = 2 * j, bB = 2 * j + 1;
        k_scatter<<<G, T, 0, 0>>>(xyz, (const float4*)rel, (const float4*)geom, bA);
        k_scatter<<<G, T, 0, sB>>>(xyz, (const float4*)rel, (const float4*)geom, bB);
        k_score<<<G, T, 0, 0>>>((float4*)out, bA);
        k_score<<<G, T, 0, sB>>>((float4*)out, bB);
        k_norm_clear<<<G, T, 0, 0>>>((float4*)out, bA);
        k_norm_clear<<<G, T, 0, sB>>>((float4*)out, bB);
    }

    // join: default stream waits for pipeline B
    cudaEventRecord(eJoin, sB);
    cudaStreamWaitEvent(0, eJoin, 0);
}